// round 2
// baseline (speedup 1.0000x reference)
#include <cuda_runtime.h>
#include <cuda_fp16.h>
#include <cstdint>
#include <cstddef>

#define TOK 8192
#define DIN 4096
#define DOUT 4096
#define RANK 16
#define NBLK (DIN / 64)
#define K_EXT 4160            // DIN + 64 (16 lora cols + 1 bias col + pad)
#define SCALING 4.0f          // 16 / sqrt(16)

#define BM 128
#define BN 256
#define BK 32
#define NSTAGE 4
#define KITER (K_EXT / BK)    // 130

#define ROWB 80                              // padded smem row stride (bytes): 5*16B, conflict-free
#define A_BYTES (BM * ROWB)                  // 10240
#define B_BYTES (BN * ROWB)                  // 20480
#define STAGE_BYTES (A_BYTES + B_BYTES)      // 30720
#define SMEM_TOTAL (NSTAGE * STAGE_BYTES)    // 122880

// Extended operand buffers (static device scratch; no runtime allocation)
__device__ __align__(1024) __half g_A[(size_t)TOK * K_EXT];   // ~68 MB
__device__ __align__(1024) __half g_B[(size_t)DOUT * K_EXT];  // ~34 MB

__constant__ float c_nf4[16] = {
    -1.0f, -0.6961928009986877f, -0.5250730514526367f, -0.39491748809814453f,
    -0.28444138169288635f, -0.18477343022823334f, -0.09105003625154495f, 0.0f,
    0.07958029955625534f, 0.16093020141124725f, 0.24611230194568634f,
    0.33791524171829224f, 0.44070982933044434f, 0.5626170039176941f,
    0.7229568362236023f, 1.0f};

// ---------------------------------------------------------------- helpers
__device__ __forceinline__ uint32_t s2u(const void* p) {
    uint32_t a;
    asm("{ .reg .u64 t; cvta.to.shared.u64 t, %1; cvt.u32.u64 %0, t; }"
        : "=r"(a) : "l"(p));
    return a;
}
__device__ __forceinline__ void cp16(uint32_t s, const void* g) {
    asm volatile("cp.async.cg.shared.global [%0], [%1], 16;" :: "r"(s), "l"(g));
}
__device__ __forceinline__ void cp_commit() {
    asm volatile("cp.async.commit_group;" ::: "memory");
}
__device__ __forceinline__ void ldsm4(uint32_t addr, uint32_t& r0, uint32_t& r1,
                                      uint32_t& r2, uint32_t& r3) {
    asm volatile("ldmatrix.sync.aligned.m8n8.x4.shared.b16 {%0,%1,%2,%3}, [%4];"
                 : "=r"(r0), "=r"(r1), "=r"(r2), "=r"(r3) : "r"(addr));
}
__device__ __forceinline__ void mma16816(float* c, uint32_t a0, uint32_t a1,
                                         uint32_t a2, uint32_t a3,
                                         uint32_t b0, uint32_t b1) {
    asm volatile(
        "mma.sync.aligned.m16n8k16.row.col.f32.f16.f16.f32 "
        "{%0,%1,%2,%3}, {%4,%5,%6,%7}, {%8,%9}, {%0,%1,%2,%3};"
        : "+f"(c[0]), "+f"(c[1]), "+f"(c[2]), "+f"(c[3])
        : "r"(a0), "r"(a1), "r"(a2), "r"(a3), "r"(b0), "r"(b1));
}

// -------------------------------------------------------- prep kernels
// x -> fp16 into g_A, plus bias-one column and zero padding of the K tail
__global__ void prep_x(const float* __restrict__ x) {
    int m = blockIdx.x;
    int tid = threadIdx.x;
    const float2* xr = (const float2*)(x + (size_t)m * DIN);
    __half2* ar2 = (__half2*)(g_A + (size_t)m * K_EXT);
    for (int k2 = tid; k2 < DIN / 2; k2 += blockDim.x) {
        float2 v = xr[k2];
        ar2[k2] = __floats2half2_rn(v.x, v.y);
    }
    __half* ar = g_A + (size_t)m * K_EXT;
    if (tid == RANK) ar[DIN + RANK] = __float2half(1.0f);
    else if (tid > RANK && tid < 64) ar[DIN + tid] = __float2half(0.0f);
}

// NF4 dequant -> fp16 into g_B, plus SCALING*lora_B column block, bias, zeros
__global__ void prep_w(const int* __restrict__ wc, const float* __restrict__ am,
                       const float* __restrict__ bias, const float* __restrict__ lb) {
    int n = blockIdx.x;
    int tid = threadIdx.x;
    const int* wr = wc + (size_t)n * DIN;
    __half* br = g_B + (size_t)n * K_EXT;
    const float* amr = am + (size_t)n * NBLK;
    for (int k2 = tid; k2 < DIN / 2; k2 += blockDim.x) {
        int k = k2 * 2;
        int2 c = ((const int2*)wr)[k2];
        float s = amr[k >> 6];
        ((__half2*)br)[k2] = __floats2half2_rn(c_nf4[c.x] * s, c_nf4[c.y] * s);
    }
    if (tid < RANK) br[DIN + tid] = __float2half(SCALING * lb[(size_t)tid * DOUT + n]);
    else if (tid == RANK) br[DIN + RANK] = __float2half(bias[n]);
    else if (tid < 64) br[DIN + tid] = __float2half(0.0f);
}

// u = x @ lora_A  (fp32), written as fp16 into g_A columns [DIN, DIN+16)
__global__ void __launch_bounds__(256) prep_lora(const float* __restrict__ x,
                                                 const float* __restrict__ la) {
    __shared__ float sA[512 * 17];  // stride 17 to kill bank conflicts
    int row_l = threadIdx.x >> 3;   // 0..31
    int kl = threadIdx.x & 7;
    size_t m = (size_t)blockIdx.x * 32 + row_l;
    const float* xr = x + m * DIN;
    float acc[16];
#pragma unroll
    for (int r = 0; r < 16; r++) acc[r] = 0.0f;
    for (int kc = 0; kc < DIN; kc += 512) {
        __syncthreads();
        for (int j = threadIdx.x; j < 512 * 16; j += 256) {
            int kk = j >> 4, rr = j & 15;
            sA[kk * 17 + rr] = la[(size_t)(kc + kk) * 16 + rr];
        }
        __syncthreads();
        for (int k = kl; k < 512; k += 8) {
            float xv = xr[kc + k];
            const float* ap = sA + k * 17;
#pragma unroll
            for (int r = 0; r < 16; r++) acc[r] += xv * ap[r];
        }
    }
#pragma unroll
    for (int r = 0; r < 16; r++) {
        acc[r] += __shfl_xor_sync(0xffffffffu, acc[r], 1);
        acc[r] += __shfl_xor_sync(0xffffffffu, acc[r], 2);
        acc[r] += __shfl_xor_sync(0xffffffffu, acc[r], 4);
    }
    __half* ar = g_A + m * K_EXT + DIN;
    ar[kl * 2] = __float2half(acc[kl * 2]);
    ar[kl * 2 + 1] = __float2half(acc[kl * 2 + 1]);
}

// -------------------------------------------------------- main GEMM
// out[TOK, DOUT] = A_ext @ B_extᵀ  via mma.sync.m16n8k16 (fp16 in, fp32 acc).
// 256 threads = 8 warps in a 2(m) x 4(n) grid of 64x64 warptiles.
__global__ void __launch_bounds__(256, 1) qlora_gemm(float* __restrict__ out) {
    extern __shared__ char smem[];
    uint32_t sb = s2u(smem);
    int tid = threadIdx.x, wid = tid >> 5, lane = tid & 31;
    int warp_m = wid & 1, warp_n = wid >> 1;

    // L2-banded CTA order: 8 m-tiles x 16 n-tiles per band (128 CTAs/band)
    int bid = (int)blockIdx.x;
    int band = bid >> 7;
    int local = bid & 127;
    int mt = band * 8 + (local & 7);   // 0..63
    int nt = local >> 3;               // 0..15

    const __half* gA = g_A + (size_t)mt * BM * K_EXT;
    const __half* gB = g_B + (size_t)nt * BN * K_EXT;

    // cp.async source pointers / smem dest offsets (6 x 16B per thread per stage)
    const __half* srcA[2];
    uint32_t dstA[2];
#pragma unroll
    for (int i = 0; i < 2; i++) {
        int idx = i * 256 + tid;           // 0..511
        int r = idx >> 2, c8 = idx & 3;    // row, 16B-chunk within BK row
        srcA[i] = gA + (size_t)r * K_EXT + c8 * 8;
        dstA[i] = r * ROWB + c8 * 16;
    }
    const __half* srcB[4];
    uint32_t dstB[4];
#pragma unroll
    for (int i = 0; i < 4; i++) {
        int idx = i * 256 + tid;           // 0..1023
        int r = idx >> 2, c8 = idx & 3;
        srcB[i] = gB + (size_t)r * K_EXT + c8 * 8;
        dstB[i] = A_BYTES + r * ROWB + c8 * 16;
    }

    // ldmatrix per-lane base offsets
    // A frag (m16k16): rows = warp_m*64 + mi*16 + (lane&15), k = k0 + (lane>>4)*8
    uint32_t aLdBase = (warp_m * 64 + (lane & 15)) * ROWB + (lane >> 4) * 16;
    // B frag x4 (two n8k16): rows = warp_n*64 + nj*16 + ((lane>>4)&1)*8 + (lane&7),
    //                        k = k0 + ((lane>>3)&1)*8
    uint32_t bLdBase = A_BYTES +
        (warp_n * 64 + ((lane >> 4) & 1) * 8 + (lane & 7)) * ROWB +
        ((lane >> 3) & 1) * 16;

    float acc[4][8][4];
#pragma unroll
    for (int mi = 0; mi < 4; mi++)
#pragma unroll
        for (int ni = 0; ni < 8; ni++)
#pragma unroll
            for (int j = 0; j < 4; j++) acc[mi][ni][j] = 0.0f;

    // ---- prologue: fill 3 stages ----
#pragma unroll
    for (int s = 0; s < NSTAGE - 1; s++) {
        uint32_t base = sb + s * STAGE_BYTES;
        int k0 = s * BK;
#pragma unroll
        for (int i = 0; i < 2; i++) cp16(base + dstA[i], srcA[i] + k0);
#pragma unroll
        for (int i = 0; i < 4; i++) cp16(base + dstB[i], srcB[i] + k0);
        cp_commit();
    }

    // ---- main loop ----
    for (int it = 0; it < KITER; ++it) {
        asm volatile("cp.async.wait_group %0;" :: "n"(NSTAGE - 2) : "memory");
        __syncthreads();

        int s = it & (NSTAGE - 1);
        uint32_t aBase = sb + s * STAGE_BYTES;
        uint32_t bBase = aBase;  // B offsets already include A_BYTES

#pragma unroll
        for (int kh = 0; kh < 2; kh++) {      // two k16 steps per BK=32
            uint32_t kOff = kh * 2 * 16;      // (k0/8)*16 with k0 = kh*16
            uint32_t a[4][4], b[8][2];
#pragma unroll
            for (int mi = 0; mi < 4; mi++)
                ldsm4(aBase + aLdBase + mi * (16 * ROWB) + kOff,
                      a[mi][0], a[mi][1], a[mi][2], a[mi][3]);
#pragma unroll
            for (int nj = 0; nj < 4; nj++)
                ldsm4(bBase + bLdBase + nj * (16 * ROWB) + kOff,
                      b[2 * nj][0], b[2 * nj][1], b[2 * nj + 1][0], b[2 * nj + 1][1]);
#pragma unroll
            for (int mi = 0; mi < 4; mi++)
#pragma unroll
                for (int ni = 0; ni < 8; ni++)
                    mma16816(acc[mi][ni], a[mi][0], a[mi][1], a[mi][2], a[mi][3],
                             b[ni][0], b[ni][1]);
        }

        // issue next stage
        int nxt = it + NSTAGE - 1;
        if (nxt < KITER) {
            uint32_t base = sb + (nxt & (NSTAGE - 1)) * STAGE_BYTES;
            int k0 = nxt * BK;
#pragma unroll
            for (int i = 0; i < 2; i++) cp16(base + dstA[i], srcA[i] + k0);
#pragma unroll
            for (int i = 0; i < 4; i++) cp16(base + dstB[i], srcB[i] + k0);
        }
        cp_commit();  // commit even when empty to keep wait_group counts aligned
    }

    // ---- epilogue: registers -> global fp32 ----
    int m0 = mt * BM + warp_m * 64 + (lane >> 2);
    int n0 = nt * BN + warp_n * 64 + (lane & 3) * 2;
#pragma unroll
    for (int mi = 0; mi < 4; mi++) {
#pragma unroll
        for (int ni = 0; ni < 8; ni++) {
            float* p0 = out + (size_t)(m0 + mi * 16) * DOUT + n0 + ni * 8;
            float* p1 = p0 + 8 * DOUT;
            float2 v0 = {acc[mi][ni][0], acc[mi][ni][1]};
            float2 v1 = {acc[mi][ni][2], acc[mi][ni][3]};
            *(float2*)p0 = v0;
            *(float2*)p1 = v1;
        }
    }
}

// -------------------------------------------------------- launch
extern "C" void kernel_launch(void* const* d_in, const int* in_sizes, int n_in,
                              void* d_out, int out_size) {
    const float* x = (const float*)d_in[0];
    const int* wc = (const int*)d_in[1];
    const float* am = (const float*)d_in[2];
    const float* bias = (const float*)d_in[3];
    const float* la = (const float*)d_in[4];
    const float* lb = (const float*)d_in[5];
    float* out = (float*)d_out;

    cudaFuncSetAttribute(qlora_gemm, cudaFuncAttributeMaxDynamicSharedMemorySize,
                         SMEM_TOTAL);

    prep_x<<<TOK, 256>>>(x);
    prep_w<<<DOUT, 256>>>(wc, am, bias, lb);
    prep_lora<<<TOK / 32, 256>>>(x, la);
    qlora_gemm<<<(TOK / BM) * (DOUT / BN), 256, SMEM_TOTAL>>>(out);
}

// round 3
// speedup vs baseline: 1.0381x; 1.0381x over previous
#include <cuda_runtime.h>
#include <cuda_fp16.h>
#include <cstdint>
#include <cstddef>

#define TOK 8192
#define DIN 4096
#define DOUT 4096
#define RANK 16
#define NBLK (DIN / 64)
#define K_EXT 4160            // DIN + 64 (16 lora cols + 1 bias col + pad)
#define SCALING 4.0f          // 16 / sqrt(16)

#define BM 128
#define BN 256
#define BK 64
#define NSTAGE 3
#define KITER (K_EXT / BK)    // 65

#define ROWB 144                             // 128B data + 16B pad; bank step 36%32=4 -> conflict-free
#define A_BYTES (BM * ROWB)                  // 18432
#define B_BYTES (BN * ROWB)                  // 36864
#define STAGE_BYTES (A_BYTES + B_BYTES)      // 55296
#define SMEM_TOTAL (NSTAGE * STAGE_BYTES)    // 165888

// Extended operand buffers (static device scratch; no runtime allocation)
__device__ __align__(1024) __half g_A[(size_t)TOK * K_EXT];   // ~68 MB
__device__ __align__(1024) __half g_B[(size_t)DOUT * K_EXT];  // ~34 MB

__constant__ float c_nf4[16] = {
    -1.0f, -0.6961928009986877f, -0.5250730514526367f, -0.39491748809814453f,
    -0.28444138169288635f, -0.18477343022823334f, -0.09105003625154495f, 0.0f,
    0.07958029955625534f, 0.16093020141124725f, 0.24611230194568634f,
    0.33791524171829224f, 0.44070982933044434f, 0.5626170039176941f,
    0.7229568362236023f, 1.0f};

// ---------------------------------------------------------------- helpers
__device__ __forceinline__ uint32_t s2u(const void* p) {
    uint32_t a;
    asm("{ .reg .u64 t; cvta.to.shared.u64 t, %1; cvt.u32.u64 %0, t; }"
        : "=r"(a) : "l"(p));
    return a;
}
__device__ __forceinline__ void cp16(uint32_t s, const void* g) {
    asm volatile("cp.async.cg.shared.global [%0], [%1], 16;" :: "r"(s), "l"(g));
}
__device__ __forceinline__ void cp_commit() {
    asm volatile("cp.async.commit_group;" ::: "memory");
}
__device__ __forceinline__ void ldsm4(uint32_t addr, uint32_t& r0, uint32_t& r1,
                                      uint32_t& r2, uint32_t& r3) {
    asm volatile("ldmatrix.sync.aligned.m8n8.x4.shared.b16 {%0,%1,%2,%3}, [%4];"
                 : "=r"(r0), "=r"(r1), "=r"(r2), "=r"(r3) : "r"(addr));
}
__device__ __forceinline__ void mma16816(float* c, const uint32_t* a,
                                         const uint32_t* b) {
    asm volatile(
        "mma.sync.aligned.m16n8k16.row.col.f32.f16.f16.f32 "
        "{%0,%1,%2,%3}, {%4,%5,%6,%7}, {%8,%9}, {%0,%1,%2,%3};"
        : "+f"(c[0]), "+f"(c[1]), "+f"(c[2]), "+f"(c[3])
        : "r"(a[0]), "r"(a[1]), "r"(a[2]), "r"(a[3]), "r"(b[0]), "r"(b[1]));
}

// -------------------------------------------------------- prep kernels
// Fused: x -> fp16 into g_A, u = x @ lora_A -> fp16 K-extension cols, bias-one,
// zero padding. One warp per token row; x read exactly once.
__global__ void __launch_bounds__(256) prep_xu(const float* __restrict__ x,
                                               const float* __restrict__ la) {
    __shared__ float sA[512 * 18];  // 36 KB; stride 18 floats -> conflict-free LDS.64
    int tid = threadIdx.x, wid = tid >> 5, lane = tid & 31;
    size_t m = (size_t)blockIdx.x * 8 + wid;
    const float* xr = x + m * DIN;
    __half* ar = g_A + m * K_EXT;
    float acc[16];
#pragma unroll
    for (int r = 0; r < 16; r++) acc[r] = 0.0f;

    for (int kc = 0; kc < DIN; kc += 512) {
        __syncthreads();
        const float4* la4 = (const float4*)(la + (size_t)kc * 16);
        for (int i = tid; i < 2048; i += 256) {
            float4 v = la4[i];
            float* d = sA + (i >> 2) * 18 + (i & 3) * 4;
            ((float2*)d)[0] = make_float2(v.x, v.y);
            ((float2*)d)[1] = make_float2(v.z, v.w);
        }
        __syncthreads();
#pragma unroll 4
        for (int ki = 0; ki < 16; ki++) {
            int k = ki * 32 + lane;
            float xv = xr[kc + k];
            ar[kc + k] = __float2half(xv);
            const float* ap = sA + k * 18;
#pragma unroll
            for (int q = 0; q < 8; q++) {
                float2 p = ((const float2*)ap)[q];
                acc[2 * q] += xv * p.x;
                acc[2 * q + 1] += xv * p.y;
            }
        }
    }
#pragma unroll
    for (int r = 0; r < 16; r++) {
        acc[r] += __shfl_xor_sync(0xffffffffu, acc[r], 16);
        acc[r] += __shfl_xor_sync(0xffffffffu, acc[r], 8);
        acc[r] += __shfl_xor_sync(0xffffffffu, acc[r], 4);
        acc[r] += __shfl_xor_sync(0xffffffffu, acc[r], 2);
        acc[r] += __shfl_xor_sync(0xffffffffu, acc[r], 1);
    }
    if (lane == 0) {
#pragma unroll
        for (int r = 0; r < 16; r++) ar[DIN + r] = __float2half(acc[r]);
    }
    // tail: bias-one at DIN+16, zeros DIN+17..DIN+63
    ar[DIN + 16 + lane] = __float2half(lane == 0 ? 1.0f : 0.0f);
    if (lane < 16) ar[DIN + 48 + lane] = __float2half(0.0f);
}

// NF4 dequant -> fp16 into g_B, plus SCALING*lora_B column block, bias, zeros
__global__ void prep_w(const int* __restrict__ wc, const float* __restrict__ am,
                       const float* __restrict__ bias, const float* __restrict__ lb) {
    int n = blockIdx.x;
    int tid = threadIdx.x;
    const int* wr = wc + (size_t)n * DIN;
    __half* br = g_B + (size_t)n * K_EXT;
    const float* amr = am + (size_t)n * NBLK;
    for (int k2 = tid; k2 < DIN / 2; k2 += blockDim.x) {
        int k = k2 * 2;
        int2 c = ((const int2*)wr)[k2];
        float s = amr[k >> 6];
        ((__half2*)br)[k2] = __floats2half2_rn(c_nf4[c.x] * s, c_nf4[c.y] * s);
    }
    if (tid < RANK) br[DIN + tid] = __float2half(SCALING * lb[(size_t)tid * DOUT + n]);
    else if (tid == RANK) br[DIN + RANK] = __float2half(bias[n]);
    else if (tid < 64) br[DIN + tid] = __float2half(0.0f);
}

// -------------------------------------------------------- main GEMM
// out[TOK, DOUT] = A_ext @ B_extᵀ  via mma.sync.m16n8k16 (fp16 in, fp32 acc).
// 256 threads = 8 warps in a 2(m) x 4(n) grid of 64x64 warptiles.
// BK=64, 3-stage cp.async pipeline, double-buffered ldmatrix fragments.
__global__ void __launch_bounds__(256, 1) qlora_gemm(float* __restrict__ out) {
    extern __shared__ char smem[];
    uint32_t sb = s2u(smem);
    int tid = threadIdx.x, wid = tid >> 5, lane = tid & 31;
    int warp_m = wid & 1, warp_n = wid >> 1;

    // L2-banded CTA order: 8 m-tiles x 16 n-tiles per band (128 CTAs/band)
    int bid = (int)blockIdx.x;
    int band = bid >> 7;
    int local = bid & 127;
    int mt = band * 8 + (local & 7);   // 0..63
    int nt = local >> 3;               // 0..15

    // cp.async base pointers (per-thread); chunk i -> +i*32 rows
    const __half* sA0 = g_A + (size_t)mt * BM * K_EXT +
                        (size_t)(tid >> 3) * K_EXT + (tid & 7) * 8;
    const __half* sB0 = g_B + (size_t)nt * BN * K_EXT +
                        (size_t)(tid >> 3) * K_EXT + (tid & 7) * 8;
    uint32_t dA0 = (uint32_t)(tid >> 3) * ROWB + (tid & 7) * 16;
    uint32_t dB0 = A_BYTES + dA0;

    // ldmatrix per-lane base offsets (within a stage)
    uint32_t aLdBase = (warp_m * 64 + (lane & 15)) * ROWB + (lane >> 4) * 16;
    uint32_t bLdBase = A_BYTES +
        (warp_n * 64 + ((lane >> 4) & 1) * 8 + (lane & 7)) * ROWB +
        ((lane >> 3) & 1) * 16;

    float acc[4][8][4];
#pragma unroll
    for (int mi = 0; mi < 4; mi++)
#pragma unroll
        for (int ni = 0; ni < 8; ni++)
#pragma unroll
            for (int j = 0; j < 4; j++) acc[mi][ni][j] = 0.0f;

#define ISSUE_STAGE(stage, kiter)                                              \
    {                                                                          \
        uint32_t base_ = sb + (stage) * STAGE_BYTES;                           \
        int k0_ = (kiter) * BK;                                                \
        _Pragma("unroll")                                                      \
        for (int i = 0; i < 4; i++)                                            \
            cp16(base_ + dA0 + i * (32 * ROWB),                                \
                 sA0 + k0_ + (size_t)i * 32 * K_EXT);                          \
        _Pragma("unroll")                                                      \
        for (int i = 0; i < 8; i++)                                            \
            cp16(base_ + dB0 + i * (32 * ROWB),                                \
                 sB0 + k0_ + (size_t)i * 32 * K_EXT);                          \
    }

    // ---- prologue: fill 2 stages ----
    ISSUE_STAGE(0, 0); cp_commit();
    ISSUE_STAGE(1, 1); cp_commit();

    int s = 0, sn = 2;
    for (int it = 0; it < KITER; ++it) {
        asm volatile("cp.async.wait_group %0;" :: "n"(1) : "memory");
        __syncthreads();

        // prefetch next stage immediately (overlaps with MMA below)
        if (it + 2 < KITER) ISSUE_STAGE(sn, it + 2);
        cp_commit();

        uint32_t aB = sb + s * STAGE_BYTES + aLdBase;
        uint32_t bB = sb + s * STAGE_BYTES + bLdBase;

        uint32_t a[2][4][4], b[2][8][2];
#pragma unroll
        for (int mi = 0; mi < 4; mi++)
            ldsm4(aB + mi * (16 * ROWB), a[0][mi][0], a[0][mi][1], a[0][mi][2], a[0][mi][3]);
#pragma unroll
        for (int nj = 0; nj < 4; nj++)
            ldsm4(bB + nj * (16 * ROWB),
                  b[0][2 * nj][0], b[0][2 * nj][1], b[0][2 * nj + 1][0], b[0][2 * nj + 1][1]);

#pragma unroll
        for (int kh = 0; kh < 4; kh++) {      // four k16 steps per BK=64
            int cur = kh & 1, nxb = cur ^ 1;
            if (kh < 3) {
                uint32_t kOff = (kh + 1) * 32;
#pragma unroll
                for (int mi = 0; mi < 4; mi++)
                    ldsm4(aB + mi * (16 * ROWB) + kOff,
                          a[nxb][mi][0], a[nxb][mi][1], a[nxb][mi][2], a[nxb][mi][3]);
#pragma unroll
                for (int nj = 0; nj < 4; nj++)
                    ldsm4(bB + nj * (16 * ROWB) + kOff,
                          b[nxb][2 * nj][0], b[nxb][2 * nj][1],
                          b[nxb][2 * nj + 1][0], b[nxb][2 * nj + 1][1]);
            }
#pragma unroll
            for (int mi = 0; mi < 4; mi++)
#pragma unroll
                for (int ni = 0; ni < 8; ni++)
                    mma16816(acc[mi][ni], a[cur][mi], b[cur][ni]);
        }

        s = (s == 2) ? 0 : s + 1;
        sn = (sn == 2) ? 0 : sn + 1;
    }

    // ---- epilogue: registers -> global fp32 ----
    int m0 = mt * BM + warp_m * 64 + (lane >> 2);
    int n0 = nt * BN + warp_n * 64 + (lane & 3) * 2;
#pragma unroll
    for (int mi = 0; mi < 4; mi++) {
#pragma unroll
        for (int ni = 0; ni < 8; ni++) {
            float* p0 = out + (size_t)(m0 + mi * 16) * DOUT + n0 + ni * 8;
            float* p1 = p0 + 8 * DOUT;
            *(float2*)p0 = make_float2(acc[mi][ni][0], acc[mi][ni][1]);
            *(float2*)p1 = make_float2(acc[mi][ni][2], acc[mi][ni][3]);
        }
    }
}

// -------------------------------------------------------- launch
extern "C" void kernel_launch(void* const* d_in, const int* in_sizes, int n_in,
                              void* d_out, int out_size) {
    const float* x = (const float*)d_in[0];
    const int* wc = (const int*)d_in[1];
    const float* am = (const float*)d_in[2];
    const float* bias = (const float*)d_in[3];
    const float* la = (const float*)d_in[4];
    const float* lb = (const float*)d_in[5];
    float* out = (float*)d_out;

    cudaFuncSetAttribute(qlora_gemm, cudaFuncAttributeMaxDynamicSharedMemorySize,
                         SMEM_TOTAL);

    prep_w<<<DOUT, 256>>>(wc, am, bias, lb);
    prep_xu<<<TOK / 8, 256>>>(x, la);
    qlora_gemm<<<(TOK / BM) * (DOUT / BN), 256, SMEM_TOTAL>>>(out);
}

// round 4
// speedup vs baseline: 1.0803x; 1.0406x over previous
#include <cuda_runtime.h>
#include <cuda_fp16.h>
#include <cstdint>
#include <cstddef>

#define TOK 8192
#define DIN 4096
#define DOUT 4096
#define RANK 16
#define NBLK (DIN / 64)
#define K_EXT 4160            // DIN + 64 (16 lora cols + 1 bias col + pad)
#define SCALING 4.0f          // 16 / sqrt(16)

#define BM 128
#define BN 128
#define BK 64
#define NSTAGE 3
#define KITER (K_EXT / BK)    // 65

#define ROWB 144                             // 128B data + 16B pad; conflict-free ldmatrix
#define A_BYTES (BM * ROWB)                  // 18432
#define B_BYTES (BN * ROWB)                  // 18432
#define STAGE_BYTES (A_BYTES + B_BYTES)      // 36864
#define SMEM_TOTAL (NSTAGE * STAGE_BYTES)    // 110592 -> 2 CTAs/SM

#define NT_TILES (DOUT / BN)                 // 32
#define MT_TILES (TOK / BM)                  // 64

// Extended operand buffers (static device scratch; no runtime allocation)
__device__ __align__(1024) __half g_A[(size_t)TOK * K_EXT];   // ~68 MB
__device__ __align__(1024) __half g_B[(size_t)DOUT * K_EXT];  // ~34 MB

__constant__ float c_nf4[16] = {
    -1.0f, -0.6961928009986877f, -0.5250730514526367f, -0.39491748809814453f,
    -0.28444138169288635f, -0.18477343022823334f, -0.09105003625154495f, 0.0f,
    0.07958029955625534f, 0.16093020141124725f, 0.24611230194568634f,
    0.33791524171829224f, 0.44070982933044434f, 0.5626170039176941f,
    0.7229568362236023f, 1.0f};

// ---------------------------------------------------------------- helpers
__device__ __forceinline__ uint32_t s2u(const void* p) {
    uint32_t a;
    asm("{ .reg .u64 t; cvta.to.shared.u64 t, %1; cvt.u32.u64 %0, t; }"
        : "=r"(a) : "l"(p));
    return a;
}
__device__ __forceinline__ void cp16(uint32_t s, const void* g) {
    asm volatile("cp.async.cg.shared.global [%0], [%1], 16;" :: "r"(s), "l"(g));
}
__device__ __forceinline__ void cp_commit() {
    asm volatile("cp.async.commit_group;" ::: "memory");
}
__device__ __forceinline__ void ldsm4(uint32_t addr, uint32_t& r0, uint32_t& r1,
                                      uint32_t& r2, uint32_t& r3) {
    asm volatile("ldmatrix.sync.aligned.m8n8.x4.shared.b16 {%0,%1,%2,%3}, [%4];"
                 : "=r"(r0), "=r"(r1), "=r"(r2), "=r"(r3) : "r"(addr));
}
__device__ __forceinline__ void mma16816(float* c, const uint32_t* a,
                                         const uint32_t* b) {
    asm volatile(
        "mma.sync.aligned.m16n8k16.row.col.f32.f16.f16.f32 "
        "{%0,%1,%2,%3}, {%4,%5,%6,%7}, {%8,%9}, {%0,%1,%2,%3};"
        : "+f"(c[0]), "+f"(c[1]), "+f"(c[2]), "+f"(c[3])
        : "r"(a[0]), "r"(a[1]), "r"(a[2]), "r"(a[3]), "r"(b[0]), "r"(b[1]));
}

// -------------------------------------------------------- fused prep kernel
// blocks [0, DOUT): NF4 dequant -> g_B (+ lora_B cols, bias, zeros)
// blocks [DOUT, DOUT + TOK/8): x -> fp16 g_A + u = x@lora_A (fused, x read once)
__global__ void __launch_bounds__(256) prep_all(
    const float* __restrict__ x, const int* __restrict__ wc,
    const float* __restrict__ am, const float* __restrict__ bias,
    const float* __restrict__ la, const float* __restrict__ lb) {
    __shared__ float sA[512 * 18];  // 36 KB (only used by the xu path)
    int tid = threadIdx.x;

    if (blockIdx.x < DOUT) {
        // ---------------- prep_w path ----------------
        int n = blockIdx.x;
        const int* wr = wc + (size_t)n * DIN;
        __half* br = g_B + (size_t)n * K_EXT;
        const float* amr = am + (size_t)n * NBLK;
        for (int k4 = tid; k4 < DIN / 4; k4 += 256) {
            int k = k4 * 4;
            int4 c = ((const int4*)wr)[k4];
            float s = amr[k >> 6];
            __half2 h0 = __floats2half2_rn(c_nf4[c.x] * s, c_nf4[c.y] * s);
            __half2 h1 = __floats2half2_rn(c_nf4[c.z] * s, c_nf4[c.w] * s);
            ((__half2*)br)[k4 * 2] = h0;
            ((__half2*)br)[k4 * 2 + 1] = h1;
        }
        if (tid < RANK) br[DIN + tid] = __float2half(SCALING * lb[(size_t)tid * DOUT + n]);
        else if (tid == RANK) br[DIN + RANK] = __float2half(bias[n]);
        else if (tid < 64) br[DIN + tid] = __float2half(0.0f);
        return;
    }

    // ---------------- prep_xu path: 8 token rows per block, 1 warp each ----
    int wid = tid >> 5, lane = tid & 31;
    size_t m = (size_t)(blockIdx.x - DOUT) * 8 + wid;
    const float* xr = x + m * DIN;
    __half* ar = g_A + m * K_EXT;
    float acc[16];
#pragma unroll
    for (int r = 0; r < 16; r++) acc[r] = 0.0f;

    for (int kc = 0; kc < DIN; kc += 512) {
        __syncthreads();
        const float4* la4 = (const float4*)(la + (size_t)kc * 16);
        for (int i = tid; i < 2048; i += 256) {
            float4 v = la4[i];
            float* d = sA + (i >> 2) * 18 + (i & 3) * 4;
            ((float2*)d)[0] = make_float2(v.x, v.y);
            ((float2*)d)[1] = make_float2(v.z, v.w);
        }
        __syncthreads();
#pragma unroll 4
        for (int ki = 0; ki < 16; ki++) {
            int k = ki * 32 + lane;
            float xv = xr[kc + k];
            ar[kc + k] = __float2half(xv);
            const float* ap = sA + k * 18;
#pragma unroll
            for (int q = 0; q < 8; q++) {
                float2 p = ((const float2*)ap)[q];
                acc[2 * q] += xv * p.x;
                acc[2 * q + 1] += xv * p.y;
            }
        }
    }
#pragma unroll
    for (int r = 0; r < 16; r++) {
        acc[r] += __shfl_xor_sync(0xffffffffu, acc[r], 16);
        acc[r] += __shfl_xor_sync(0xffffffffu, acc[r], 8);
        acc[r] += __shfl_xor_sync(0xffffffffu, acc[r], 4);
        acc[r] += __shfl_xor_sync(0xffffffffu, acc[r], 2);
        acc[r] += __shfl_xor_sync(0xffffffffu, acc[r], 1);
    }
    if (lane == 0) {
#pragma unroll
        for (int r = 0; r < 16; r++) ar[DIN + r] = __float2half(acc[r]);
    }
    ar[DIN + 16 + lane] = __float2half(lane == 0 ? 1.0f : 0.0f);
    if (lane < 16) ar[DIN + 48 + lane] = __float2half(0.0f);
}

// -------------------------------------------------------- main GEMM
// out[TOK, DOUT] = A_ext @ B_extᵀ via mma.sync.m16n8k16 (fp16 in, fp32 acc).
// 128 threads = 4 warps (2x2 of 64x64 warptiles). 2 CTAs/SM so pipeline
// bubbles of one CTA are covered by the other's tensor work.
__global__ void __launch_bounds__(128, 2) qlora_gemm(float* __restrict__ out) {
    extern __shared__ char smem[];
    uint32_t sb = s2u(smem);
    int tid = threadIdx.x, wid = tid >> 5, lane = tid & 31;
    int warp_m = wid & 1, warp_n = wid >> 1;   // 2 x 2

    // L2-banded CTA order: 8 m-tiles x 32 n-tiles per band (256 CTAs/band)
    int bid = (int)blockIdx.x;
    int band = bid >> 8;
    int local = bid & 255;
    int mt = band * 8 + (local & 7);   // 0..63
    int nt = local >> 3;               // 0..31

    // cp.async: 128 threads, 8 x 16B chunks per row-group of 16 rows
    const __half* sA0 = g_A + (size_t)mt * BM * K_EXT +
                        (size_t)(tid >> 3) * K_EXT + (tid & 7) * 8;
    const __half* sB0 = g_B + (size_t)nt * BN * K_EXT +
                        (size_t)(tid >> 3) * K_EXT + (tid & 7) * 8;
    uint32_t dA0 = (uint32_t)(tid >> 3) * ROWB + (tid & 7) * 16;
    uint32_t dB0 = A_BYTES + dA0;

    uint32_t aLdBase = (warp_m * 64 + (lane & 15)) * ROWB + (lane >> 4) * 16;
    uint32_t bLdBase = A_BYTES +
        (warp_n * 64 + ((lane >> 4) & 1) * 8 + (lane & 7)) * ROWB +
        ((lane >> 3) & 1) * 16;

    float acc[4][8][4];
#pragma unroll
    for (int mi = 0; mi < 4; mi++)
#pragma unroll
        for (int ni = 0; ni < 8; ni++)
#pragma unroll
            for (int j = 0; j < 4; j++) acc[mi][ni][j] = 0.0f;

#define ISSUE_STAGE(stage, kiter)                                              \
    {                                                                          \
        uint32_t base_ = sb + (stage) * STAGE_BYTES;                           \
        int k0_ = (kiter) * BK;                                                \
        _Pragma("unroll")                                                      \
        for (int i = 0; i < 8; i++)                                            \
            cp16(base_ + dA0 + i * (16 * ROWB),                                \
                 sA0 + k0_ + (size_t)i * 16 * K_EXT);                          \
        _Pragma("unroll")                                                      \
        for (int i = 0; i < 8; i++)                                            \
            cp16(base_ + dB0 + i * (16 * ROWB),                                \
                 sB0 + k0_ + (size_t)i * 16 * K_EXT);                          \
    }

    // ---- prologue: fill 2 stages ----
    ISSUE_STAGE(0, 0); cp_commit();
    ISSUE_STAGE(1, 1); cp_commit();

    int s = 0, sn = 2;
    for (int it = 0; it < KITER; ++it) {
        asm volatile("cp.async.wait_group %0;" :: "n"(1) : "memory");
        __syncthreads();

        // prefetch next stage immediately (overlaps with MMA below)
        if (it + 2 < KITER) ISSUE_STAGE(sn, it + 2);
        cp_commit();

        uint32_t aB = sb + s * STAGE_BYTES + aLdBase;
        uint32_t bB = sb + s * STAGE_BYTES + bLdBase;

#pragma unroll
        for (int kh = 0; kh < 4; kh++) {      // four k16 steps per BK=64
            uint32_t kOff = kh * 32;
            uint32_t a[4][4], b[8][2];
#pragma unroll
            for (int mi = 0; mi < 4; mi++)
                ldsm4(aB + mi * (16 * ROWB) + kOff,
                      a[mi][0], a[mi][1], a[mi][2], a[mi][3]);
#pragma unroll
            for (int nj = 0; nj < 4; nj++)
                ldsm4(bB + nj * (16 * ROWB) + kOff,
                      b[2 * nj][0], b[2 * nj][1], b[2 * nj + 1][0], b[2 * nj + 1][1]);
#pragma unroll
            for (int mi = 0; mi < 4; mi++)
#pragma unroll
                for (int ni = 0; ni < 8; ni++)
                    mma16816(acc[mi][ni], a[mi], b[ni]);
        }

        s = (s == 2) ? 0 : s + 1;
        sn = (sn == 2) ? 0 : sn + 1;
    }

    // ---- epilogue: registers -> global fp32 ----
    int m0 = mt * BM + warp_m * 64 + (lane >> 2);
    int n0 = nt * BN + warp_n * 64 + (lane & 3) * 2;
#pragma unroll
    for (int mi = 0; mi < 4; mi++) {
#pragma unroll
        for (int ni = 0; ni < 8; ni++) {
            float* p0 = out + (size_t)(m0 + mi * 16) * DOUT + n0 + ni * 8;
            float* p1 = p0 + 8 * DOUT;
            *(float2*)p0 = make_float2(acc[mi][ni][0], acc[mi][ni][1]);
            *(float2*)p1 = make_float2(acc[mi][ni][2], acc[mi][ni][3]);
        }
    }
}

// -------------------------------------------------------- launch
extern "C" void kernel_launch(void* const* d_in, const int* in_sizes, int n_in,
                              void* d_out, int out_size) {
    const float* x = (const float*)d_in[0];
    const int* wc = (const int*)d_in[1];
    const float* am = (const float*)d_in[2];
    const float* bias = (const float*)d_in[3];
    const float* la = (const float*)d_in[4];
    const float* lb = (const float*)d_in[5];
    float* out = (float*)d_out;

    cudaFuncSetAttribute(qlora_gemm, cudaFuncAttributeMaxDynamicSharedMemorySize,
                         SMEM_TOTAL);

    prep_all<<<DOUT + TOK / 8, 256>>>(x, wc, am, bias, la, lb);
    qlora_gemm<<<MT_TILES * NT_TILES, 128, SMEM_TOTAL>>>(out);
}